// round 1
// baseline (speedup 1.0000x reference)
#include <cuda_runtime.h>
#include <cuda_bf16.h>
#include <math.h>

// Shapes
#define BATCH 8
#define CDIM  1024      // channels == tokens
#define SPAT  1024      // 32*32 spatial == feature dim
#define NH    16
#define HD    64
#define K9    9216      // 1024*9 conv GEMM K

// ---------------- scratch (device globals; no allocations allowed) ---------
__device__ float g_qc[(size_t)BATCH * CDIM * SPAT];     // conv outs [b][c][spatial]
__device__ float g_kc[(size_t)BATCH * CDIM * SPAT];
__device__ float g_vc[(size_t)BATCH * CDIM * SPAT];
__device__ float g_ao[(size_t)BATCH * CDIM * SPAT];     // attention merged out [b][t][f]
__device__ float g_wt[(size_t)3 * K9 * CDIM];           // transposed weights [which][r][i][o]
__device__ float g_attn[(size_t)BATCH * NH * CDIM * CDIM]; // S / P in place (512 MB)

// ---------------- weight transpose: W[o][i][3][3] -> Wt[r][i][o] -----------
__global__ void transpose_w(const float* __restrict__ W, float* __restrict__ Wt) {
    __shared__ float tile[32][33];
    int kb = blockIdx.x * 32;   // k9 = i*9 + r
    int ob = blockIdx.y * 32;   // o
    int tx = threadIdx.x, ty = threadIdx.y;   // (32, 8)
    #pragma unroll
    for (int r = ty; r < 32; r += 8)
        tile[r][tx] = W[(size_t)(ob + r) * K9 + kb + tx];
    __syncthreads();
    #pragma unroll
    for (int r = ty; r < 32; r += 8) {
        int k9 = kb + r;
        int i = k9 / 9;
        int rr = k9 - i * 9;
        Wt[((size_t)rr * CDIM + i) * CDIM + ob + tx] = tile[tx][r];
    }
}

// ---------------- conv3x3 as implicit GEMM ---------------------------------
// out[b][o][pix] = bias[o] + sum_{r,i} Wt[r][i][o] * in[b][i][shift_r(pix)]
// M = o (1024), N = pix (1024), K = r*1024+i (9216). BM=BN=128, BK=8.
__global__ __launch_bounds__(256, 2)
void conv_gemm(const float* __restrict__ Wt, const float* __restrict__ bias,
               const float* __restrict__ in, float* __restrict__ out) {
    __shared__ float As[8][128];
    __shared__ float Bs[8][128];
    const int b  = blockIdx.z;
    const int m0 = blockIdx.y * 128;
    const int n0 = blockIdx.x * 128;
    const int tid = threadIdx.x;
    const int ty = tid >> 4, tx = tid & 15;

    const float* inb = in + (size_t)b * CDIM * SPAT;
    float acc[8][8];
    #pragma unroll
    for (int i = 0; i < 8; i++)
        #pragma unroll
        for (int j = 0; j < 8; j++) acc[i][j] = 0.f;

    // load assignments
    const int lk = tid >> 5;            // k' (0..7) for both tiles
    const int am = (tid * 4) & 127;     // A col base (4 contiguous)
    const int bn = am;                  // B col base (4 contiguous)
    const int pix = n0 + bn;
    const int py = pix >> 5;            // row of first of the 4 pixels (same for all 4)
    const int px = pix & 31;

    for (int kk = 0; kk < K9; kk += 8) {
        int r  = kk >> 10;              // constant within the BK=8 slice
        int i0 = kk & 1023;
        int dy = r / 3 - 1;
        int dx = r - (r / 3) * 3 - 1;

        // A tile: Wt[(kk+lk)*1024 + m0+am ...] contiguous
        *(float4*)&As[lk][am] = *(const float4*)&Wt[(size_t)(kk + lk) * CDIM + m0 + am];

        // B tile: shifted input with zero padding
        {
            int yy = py + dy;
            bool yok = ((unsigned)yy) < 32u;
            const float* src = inb + (size_t)(i0 + lk) * SPAT + yy * 32;
            #pragma unroll
            for (int j = 0; j < 4; j++) {
                int xx = px + dx + j;
                Bs[lk][bn + j] = (yok && ((unsigned)xx) < 32u) ? src[xx] : 0.f;
            }
        }
        __syncthreads();

        #pragma unroll
        for (int k = 0; k < 8; k++) {
            float4 a0 = *(const float4*)&As[k][ty * 8];
            float4 a1 = *(const float4*)&As[k][ty * 8 + 4];
            float4 b0 = *(const float4*)&Bs[k][tx * 8];
            float4 b1 = *(const float4*)&Bs[k][tx * 8 + 4];
            float av[8] = {a0.x, a0.y, a0.z, a0.w, a1.x, a1.y, a1.z, a1.w};
            float bv[8] = {b0.x, b0.y, b0.z, b0.w, b1.x, b1.y, b1.z, b1.w};
            #pragma unroll
            for (int i = 0; i < 8; i++)
                #pragma unroll
                for (int j = 0; j < 8; j++)
                    acc[i][j] += av[i] * bv[j];
        }
        __syncthreads();
    }

    #pragma unroll
    for (int i = 0; i < 8; i++) {
        int m = m0 + ty * 8 + i;
        float bi = bias[m];
        float4 o0 = {acc[i][0] + bi, acc[i][1] + bi, acc[i][2] + bi, acc[i][3] + bi};
        float4 o1 = {acc[i][4] + bi, acc[i][5] + bi, acc[i][6] + bi, acc[i][7] + bi};
        float* op = out + (size_t)(b * CDIM + m) * SPAT + n0 + tx * 8;
        *(float4*)op = o0;
        *(float4*)(op + 4) = o1;
    }
}

// ---------------- S = scale * Q K^T, masked --------------------------------
// per (b,h): M=1024 (t), N=1024 (s), K=64. BM=BN=128, BK=16.
__global__ __launch_bounds__(256, 2)
void attn_qk(const float* __restrict__ qc, const float* __restrict__ kc,
             const int* __restrict__ mask, float* __restrict__ S) {
    __shared__ float Qs[16][128];
    __shared__ float Ks[16][128];
    const int bh = blockIdx.z;
    const int b = bh >> 4, h = bh & 15;
    const int t0 = blockIdx.y * 128;
    const int s0 = blockIdx.x * 128;
    const int tid = threadIdx.x;
    const int ty = tid >> 4, tx = tid & 15;

    const float* qp = qc + (size_t)b * CDIM * SPAT + h * HD;
    const float* kp = kc + (size_t)b * CDIM * SPAT + h * HD;
    const int th = tid >> 1;
    const int kq = (tid & 1) * 8;

    float acc[8][8];
    #pragma unroll
    for (int i = 0; i < 8; i++)
        #pragma unroll
        for (int j = 0; j < 8; j++) acc[i][j] = 0.f;

    for (int kk = 0; kk < HD; kk += 16) {
        float4 q0 = *(const float4*)(qp + (size_t)(t0 + th) * SPAT + kk + kq);
        float4 q1 = *(const float4*)(qp + (size_t)(t0 + th) * SPAT + kk + kq + 4);
        Qs[kq + 0][th] = q0.x; Qs[kq + 1][th] = q0.y; Qs[kq + 2][th] = q0.z; Qs[kq + 3][th] = q0.w;
        Qs[kq + 4][th] = q1.x; Qs[kq + 5][th] = q1.y; Qs[kq + 6][th] = q1.z; Qs[kq + 7][th] = q1.w;
        float4 k0 = *(const float4*)(kp + (size_t)(s0 + th) * SPAT + kk + kq);
        float4 k1 = *(const float4*)(kp + (size_t)(s0 + th) * SPAT + kk + kq + 4);
        Ks[kq + 0][th] = k0.x; Ks[kq + 1][th] = k0.y; Ks[kq + 2][th] = k0.z; Ks[kq + 3][th] = k0.w;
        Ks[kq + 4][th] = k1.x; Ks[kq + 5][th] = k1.y; Ks[kq + 6][th] = k1.z; Ks[kq + 7][th] = k1.w;
        __syncthreads();
        #pragma unroll
        for (int k = 0; k < 16; k++) {
            float4 a0 = *(const float4*)&Qs[k][ty * 8];
            float4 a1 = *(const float4*)&Qs[k][ty * 8 + 4];
            float4 b0 = *(const float4*)&Ks[k][tx * 8];
            float4 b1 = *(const float4*)&Ks[k][tx * 8 + 4];
            float av[8] = {a0.x, a0.y, a0.z, a0.w, a1.x, a1.y, a1.z, a1.w};
            float bv[8] = {b0.x, b0.y, b0.z, b0.w, b1.x, b1.y, b1.z, b1.w};
            #pragma unroll
            for (int i = 0; i < 8; i++)
                #pragma unroll
                for (int j = 0; j < 8; j++)
                    acc[i][j] += av[i] * bv[j];
        }
        __syncthreads();
    }

    float* Srow = S + (size_t)bh * CDIM * CDIM;
    const int* mrow = mask + (size_t)b * CDIM * CDIM;
    #pragma unroll
    for (int i = 0; i < 8; i++) {
        int t = t0 + ty * 8 + i;
        #pragma unroll
        for (int j = 0; j < 8; j++) {
            int s = s0 + tx * 8 + j;
            int mv = mrow[(size_t)t * CDIM + s];
            Srow[(size_t)t * CDIM + s] = mv ? acc[i][j] * 0.125f : -1e9f;
        }
    }
}

// ---------------- row softmax over 1024, in place --------------------------
__global__ __launch_bounds__(256)
void softmax_rows(float* __restrict__ S) {
    __shared__ float red[8];
    const int t = threadIdx.x;
    float4* p = (float4*)(S + (size_t)blockIdx.x * 1024);
    float4 v = p[t];
    float m = fmaxf(fmaxf(v.x, v.y), fmaxf(v.z, v.w));
    #pragma unroll
    for (int o = 16; o > 0; o >>= 1) m = fmaxf(m, __shfl_xor_sync(0xffffffffu, m, o));
    if ((t & 31) == 0) red[t >> 5] = m;
    __syncthreads();
    m = red[0];
    #pragma unroll
    for (int i = 1; i < 8; i++) m = fmaxf(m, red[i]);
    __syncthreads();
    v.x = __expf(v.x - m); v.y = __expf(v.y - m);
    v.z = __expf(v.z - m); v.w = __expf(v.w - m);
    float s = v.x + v.y + v.z + v.w;
    #pragma unroll
    for (int o = 16; o > 0; o >>= 1) s += __shfl_xor_sync(0xffffffffu, s, o);
    if ((t & 31) == 0) red[t >> 5] = s;
    __syncthreads();
    s = red[0];
    #pragma unroll
    for (int i = 1; i < 8; i++) s += red[i];
    float r = 1.0f / s;
    v.x *= r; v.y *= r; v.z *= r; v.w *= r;
    p[t] = v;
}

// ---------------- O = P V, write merged [b][t][h*64+j] ---------------------
// per (b,h): M=1024 (t), N=64 (j), K=1024 (s). BM=128, BN=64, BK=16.
__global__ __launch_bounds__(256, 2)
void attn_pv(const float* __restrict__ P, const float* __restrict__ vc,
             float* __restrict__ ao) {
    __shared__ float Ps[16][128];
    __shared__ float Vs[16][64];
    const int bh = blockIdx.z;
    const int b = bh >> 4, h = bh & 15;
    const int t0 = blockIdx.y * 128;
    const int tid = threadIdx.x;
    const int ty = tid >> 4, tx = tid & 15;

    const float* Pp = P + (size_t)bh * CDIM * CDIM;
    const float* vp = vc + (size_t)b * CDIM * SPAT + h * HD;

    float acc[8][4];
    #pragma unroll
    for (int i = 0; i < 8; i++)
        #pragma unroll
        for (int j = 0; j < 4; j++) acc[i][j] = 0.f;

    const int th = tid >> 1;
    const int kq = (tid & 1) * 8;
    const int vk = tid >> 4;
    const int vj = (tid & 15) * 4;

    for (int kk = 0; kk < CDIM; kk += 16) {
        float4 p0 = *(const float4*)(Pp + (size_t)(t0 + th) * CDIM + kk + kq);
        float4 p1 = *(const float4*)(Pp + (size_t)(t0 + th) * CDIM + kk + kq + 4);
        Ps[kq + 0][th] = p0.x; Ps[kq + 1][th] = p0.y; Ps[kq + 2][th] = p0.z; Ps[kq + 3][th] = p0.w;
        Ps[kq + 4][th] = p1.x; Ps[kq + 5][th] = p1.y; Ps[kq + 6][th] = p1.z; Ps[kq + 7][th] = p1.w;
        *(float4*)&Vs[vk][vj] = *(const float4*)(vp + (size_t)(kk + vk) * SPAT + vj);
        __syncthreads();
        #pragma unroll
        for (int k = 0; k < 16; k++) {
            float4 bv = *(const float4*)&Vs[k][tx * 4];
            float4 a0 = *(const float4*)&Ps[k][ty * 8];
            float4 a1 = *(const float4*)&Ps[k][ty * 8 + 4];
            float av[8] = {a0.x, a0.y, a0.z, a0.w, a1.x, a1.y, a1.z, a1.w};
            #pragma unroll
            for (int i = 0; i < 8; i++) {
                acc[i][0] += av[i] * bv.x;
                acc[i][1] += av[i] * bv.y;
                acc[i][2] += av[i] * bv.z;
                acc[i][3] += av[i] * bv.w;
            }
        }
        __syncthreads();
    }

    float* aop = ao + (size_t)b * CDIM * SPAT + h * HD;
    #pragma unroll
    for (int i = 0; i < 8; i++) {
        int t = t0 + ty * 8 + i;
        float4 o0 = {acc[i][0], acc[i][1], acc[i][2], acc[i][3]};
        *(float4*)(aop + (size_t)t * SPAT + tx * 4) = o0;
    }
}

// ---------------- output projection: Y = A Wo^T + bo -----------------------
// A: [8192][1024] row-major, Wo: [1024][1024] row-major. BM=BN=128, BK=8.
__global__ __launch_bounds__(256, 2)
void proj_gemm(const float* __restrict__ A, const float* __restrict__ Wo,
               const float* __restrict__ bo, float* __restrict__ out) {
    __shared__ float As[8][128];
    __shared__ float Bs[8][128];
    const int row0 = blockIdx.y * 128;
    const int m0 = blockIdx.x * 128;
    const int tid = threadIdx.x;
    const int ty = tid >> 4, tx = tid & 15;
    const int th = tid >> 1;
    const int kq = (tid & 1) * 4;

    float acc[8][8];
    #pragma unroll
    for (int i = 0; i < 8; i++)
        #pragma unroll
        for (int j = 0; j < 8; j++) acc[i][j] = 0.f;

    for (int kk = 0; kk < 1024; kk += 8) {
        float4 a = *(const float4*)(A + (size_t)(row0 + th) * 1024 + kk + kq);
        As[kq + 0][th] = a.x; As[kq + 1][th] = a.y; As[kq + 2][th] = a.z; As[kq + 3][th] = a.w;
        float4 w = *(const float4*)(Wo + (size_t)(m0 + th) * 1024 + kk + kq);
        Bs[kq + 0][th] = w.x; Bs[kq + 1][th] = w.y; Bs[kq + 2][th] = w.z; Bs[kq + 3][th] = w.w;
        __syncthreads();
        #pragma unroll
        for (int k = 0; k < 8; k++) {
            float4 a0 = *(const float4*)&As[k][ty * 8];
            float4 a1 = *(const float4*)&As[k][ty * 8 + 4];
            float4 b0 = *(const float4*)&Bs[k][tx * 8];
            float4 b1 = *(const float4*)&Bs[k][tx * 8 + 4];
            float av[8] = {a0.x, a0.y, a0.z, a0.w, a1.x, a1.y, a1.z, a1.w};
            float bv[8] = {b0.x, b0.y, b0.z, b0.w, b1.x, b1.y, b1.z, b1.w};
            #pragma unroll
            for (int i = 0; i < 8; i++)
                #pragma unroll
                for (int j = 0; j < 8; j++)
                    acc[i][j] += av[i] * bv[j];
        }
        __syncthreads();
    }

    #pragma unroll
    for (int i = 0; i < 8; i++) {
        int rr = row0 + ty * 8 + i;
        float* op = out + (size_t)rr * 1024 + m0 + tx * 8;
        float4 o0 = {acc[i][0] + bo[m0 + tx * 8 + 0], acc[i][1] + bo[m0 + tx * 8 + 1],
                     acc[i][2] + bo[m0 + tx * 8 + 2], acc[i][3] + bo[m0 + tx * 8 + 3]};
        float4 o1 = {acc[i][4] + bo[m0 + tx * 8 + 4], acc[i][5] + bo[m0 + tx * 8 + 5],
                     acc[i][6] + bo[m0 + tx * 8 + 6], acc[i][7] + bo[m0 + tx * 8 + 7]};
        *(float4*)op = o0;
        *(float4*)(op + 4) = o1;
    }
}

// ---------------- launch ---------------------------------------------------
extern "C" void kernel_launch(void* const* d_in, const int* in_sizes, int n_in,
                              void* d_out, int out_size) {
    const float* q  = (const float*)d_in[0];
    const float* k  = (const float*)d_in[1];
    const float* v  = (const float*)d_in[2];
    const float* Wq = (const float*)d_in[3];
    const float* bq = (const float*)d_in[4];
    const float* Wk = (const float*)d_in[5];
    const float* bk = (const float*)d_in[6];
    const float* Wv = (const float*)d_in[7];
    const float* bv = (const float*)d_in[8];
    const float* Wo = (const float*)d_in[9];
    const float* bo = (const float*)d_in[10];
    const int*   mask = (const int*)d_in[11];
    float* out = (float*)d_out;

    float *qc, *kc, *vc, *ao, *wt, *attn;
    cudaGetSymbolAddress((void**)&qc, g_qc);
    cudaGetSymbolAddress((void**)&kc, g_kc);
    cudaGetSymbolAddress((void**)&vc, g_vc);
    cudaGetSymbolAddress((void**)&ao, g_ao);
    cudaGetSymbolAddress((void**)&wt, g_wt);
    cudaGetSymbolAddress((void**)&attn, g_attn);

    float* wt_q = wt;
    float* wt_k = wt + (size_t)K9 * CDIM;
    float* wt_v = wt + (size_t)2 * K9 * CDIM;

    dim3 tpb(32, 8);
    dim3 tgrid(K9 / 32, CDIM / 32);
    transpose_w<<<tgrid, tpb>>>(Wq, wt_q);
    transpose_w<<<tgrid, tpb>>>(Wk, wt_k);
    transpose_w<<<tgrid, tpb>>>(Wv, wt_v);

    dim3 cgrid(8, 8, BATCH);
    conv_gemm<<<cgrid, 256>>>(wt_q, bq, q, qc);
    conv_gemm<<<cgrid, 256>>>(wt_k, bk, k, kc);
    conv_gemm<<<cgrid, 256>>>(wt_v, bv, v, vc);

    attn_qk<<<dim3(8, 8, BATCH * NH), 256>>>(qc, kc, mask, attn);
    softmax_rows<<<BATCH * NH * CDIM, 256>>>(attn);
    attn_pv<<<dim3(1, 8, BATCH * NH), 256>>>(attn, vc, ao);

    proj_gemm<<<dim3(8, 64), 256>>>(ao, Wo, bo, out);
}

// round 3
// speedup vs baseline: 2.7697x; 2.7697x over previous
#include <cuda_runtime.h>
#include <cuda_bf16.h>
#include <cstdint>
#include <math.h>

// Shapes
#define BATCH 8
#define CDIM  1024      // channels == tokens
#define SPAT  1024      // 32*32 spatial
#define NH    16
#define HD    64
#define CONVK 9216      // 1024*9

// ---------------- scratch (device globals) ---------------------------------
__device__ __nv_bfloat16 g_whi[(size_t)3 * CDIM * CONVK];   // [conv][o][r*1024+i]
__device__ __nv_bfloat16 g_wlo[(size_t)3 * CDIM * CONVK];
__device__ __nv_bfloat16 g_ihi[(size_t)24 * SPAT * CDIM];   // [conv*8+b][pix][i]
__device__ __nv_bfloat16 g_ilo[(size_t)24 * SPAT * CDIM];
__device__ float g_cout[(size_t)24 * CDIM * SPAT];          // [conv][b][o][pix]
__device__ float g_ao[(size_t)BATCH * CDIM * SPAT];
__device__ float g_attn[(size_t)BATCH * NH * CDIM * CDIM];

// ---------------- PTX helpers (sm_80-baseline only) ------------------------
__device__ __forceinline__ uint32_t smem_to_u32(const void* p) {
    uint32_t a;
    asm("{ .reg .u64 t; cvta.to.shared.u64 t, %1; cvt.u32.u64 %0, t; }" : "=r"(a) : "l"(p));
    return a;
}
__device__ __forceinline__ void cp_async16(uint32_t dst, const void* src, int src_bytes) {
    asm volatile("cp.async.cg.shared.global [%0], [%1], 16, %2;"
                 :: "r"(dst), "l"(src), "r"(src_bytes) : "memory");
}
#define CP_COMMIT() asm volatile("cp.async.commit_group;" ::: "memory")
#define CP_WAIT0()  asm volatile("cp.async.wait_group 0;" ::: "memory")

#define LDSM_X4(r, a) \
    asm volatile("ldmatrix.sync.aligned.m8n8.x4.shared.b16 {%0,%1,%2,%3}, [%4];" \
                 : "=r"((r)[0]), "=r"((r)[1]), "=r"((r)[2]), "=r"((r)[3]) : "r"(a))

__device__ __forceinline__ void mma16816(float* c, const uint32_t* a, uint32_t b0, uint32_t b1) {
    asm volatile("mma.sync.aligned.m16n8k16.row.col.f32.bf16.bf16.f32 "
                 "{%0,%1,%2,%3},{%4,%5,%6,%7},{%8,%9},{%0,%1,%2,%3};"
                 : "+f"(c[0]), "+f"(c[1]), "+f"(c[2]), "+f"(c[3])
                 : "r"(a[0]), "r"(a[1]), "r"(a[2]), "r"(a[3]), "r"(b0), "r"(b1));
}

// ---------------- precompute: weight split to [o][r*1024+i] ----------------
__global__ void split_w(const float* __restrict__ Wq, const float* __restrict__ Wk,
                        const float* __restrict__ Wv,
                        __nv_bfloat16* __restrict__ hi, __nv_bfloat16* __restrict__ lo) {
    const int o = blockIdx.x, conv = blockIdx.y;
    const float* W = (conv == 0 ? Wq : (conv == 1 ? Wk : Wv)) + (size_t)o * CONVK;
    size_t ob = ((size_t)conv * CDIM + o) * CONVK;
    for (int kk = threadIdx.x; kk < CONVK; kk += 256) {
        int r = kk >> 10, i = kk & 1023;
        float w = W[i * 9 + r];
        __nv_bfloat16 h = __float2bfloat16(w);
        hi[ob + kk] = h;
        lo[ob + kk] = __float2bfloat16(w - __bfloat162float(h));
    }
}

// ---------------- precompute: transpose + split inputs ---------------------
__global__ void transpose_split_in(const float* __restrict__ q, const float* __restrict__ k,
                                   const float* __restrict__ v,
                                   __nv_bfloat16* __restrict__ hi, __nv_bfloat16* __restrict__ lo) {
    __shared__ float t[32][33];
    const int z = blockIdx.z, conv = z >> 3, b = z & 7;
    const float* src = (conv == 0 ? q : (conv == 1 ? k : v)) + (size_t)b * CDIM * SPAT;
    const int i0 = blockIdx.y * 32, p0 = blockIdx.x * 32;
    const int tx = threadIdx.x, ty = threadIdx.y;
    #pragma unroll
    for (int r = ty; r < 32; r += 8) t[r][tx] = src[(size_t)(i0 + r) * SPAT + p0 + tx];
    __syncthreads();
    size_t base = (size_t)z * SPAT * CDIM;
    #pragma unroll
    for (int r = ty; r < 32; r += 8) {
        float w = t[tx][r];
        __nv_bfloat16 h = __float2bfloat16(w);
        size_t idx = base + (size_t)(p0 + r) * CDIM + i0 + tx;
        hi[idx] = h;
        lo[idx] = __float2bfloat16(w - __bfloat162float(h));
    }
}

// ---------------- conv via warp MMA (M=128 o, N=128 pix, K=9216x{3 terms}) -
// SMEM stage (64KB): Ahi[128][64] | Alo | Bhi | Blo  (bf16, 128B rows, XOR swizzle)
#define CM_SMEM 65536
#define CM_NIT  144

__global__ __launch_bounds__(256, 2)
void conv_mma(const __nv_bfloat16* __restrict__ whi, const __nv_bfloat16* __restrict__ wlo,
              const __nv_bfloat16* __restrict__ ihi, const __nv_bfloat16* __restrict__ ilo,
              const float* __restrict__ bq, const float* __restrict__ bk,
              const float* __restrict__ bv, float* __restrict__ cout) {
    extern __shared__ char smem[];
    const uint32_t sb = smem_to_u32(smem);
    const int tid = threadIdx.x, wid = tid >> 5, lane = tid & 31;
    const int z = blockIdx.z, conv = z >> 3;
    const int m0 = blockIdx.y * 128, n0 = blockIdx.x * 128;

    const __nv_bfloat16* Ah = whi + ((size_t)conv * CDIM + m0) * CONVK;
    const __nv_bfloat16* Al = wlo + ((size_t)conv * CDIM + m0) * CONVK;
    const __nv_bfloat16* Ih = ihi + (size_t)z * SPAT * CDIM;
    const __nv_bfloat16* Il = ilo + (size_t)z * SPAT * CDIM;

    const uint32_t sAh = sb, sAl = sb + 16384, sBh = sb + 32768, sBl = sb + 49152;

    // warp tile: 32(m) x 64(n); warps 4x2
    const int wm = (wid & 3) * 32, wn = (wid >> 2) * 64;

    float acc[2][8][4];
    #pragma unroll
    for (int i = 0; i < 2; i++)
        #pragma unroll
        for (int j = 0; j < 8; j++)
            #pragma unroll
            for (int q = 0; q < 4; q++) acc[i][j][q] = 0.f;

    // ldmatrix source addresses (lane-dependent parts)
    const int lrow = lane & 15;            // row within 16-row group
    const int lkc  = lane >> 4;            // 0/1 -> +8 k elements (1 chunk)

    for (int it = 0; it < CM_NIT; it++) {
        // ---------------- load stage ----------------
        const int r = it >> 4;
        const int dy = r / 3 - 1, dx = r % 3 - 1;
        const int i0 = (it & 15) << 6;
        #pragma unroll
        for (int p = 0; p < 4; p++) {
            int ci = tid + p * 256;                    // 0..1023
            int row = ci >> 3, c = ci & 7;
            uint32_t off = (uint32_t)row * 128 + ((uint32_t)(c ^ (row & 7)) << 4);
            const __nv_bfloat16* as = Ah + (size_t)row * CONVK + it * 64 + c * 8;
            const __nv_bfloat16* ls = Al + (size_t)row * CONVK + it * 64 + c * 8;
            cp_async16(sAh + off, as, 16);
            cp_async16(sAl + off, ls, 16);
            int pix = n0 + row;
            int y = (pix >> 5) + dy, x = (pix & 31) + dx;
            bool ok = ((unsigned)y < 32u) && ((unsigned)x < 32u);
            int sp = ok ? (y * 32 + x) : 0;
            int nb = ok ? 16 : 0;
            cp_async16(sBh + off, Ih + (size_t)sp * CDIM + i0 + c * 8, nb);
            cp_async16(sBl + off, Il + (size_t)sp * CDIM + i0 + c * 8, nb);
        }
        CP_COMMIT();
        CP_WAIT0();
        __syncthreads();

        // ---------------- compute: 4 k16-steps x 3 products ----------------
        #pragma unroll
        for (int ks = 0; ks < 4; ks++) {
            const int kc = ks * 2 + lkc;   // 16B chunk index within row
            uint32_t ah[2][4], al[2][4], b[4][4];

            #pragma unroll
            for (int mf = 0; mf < 2; mf++) {
                int row = wm + mf * 16 + lrow;
                uint32_t addr = (uint32_t)row * 128 + ((uint32_t)(kc ^ (row & 7)) << 4);
                LDSM_X4(ah[mf], sAh + addr);
            }
            #pragma unroll
            for (int np = 0; np < 4; np++) {
                int row = wn + np * 16 + lrow;
                uint32_t addr = (uint32_t)row * 128 + ((uint32_t)(kc ^ (row & 7)) << 4);
                LDSM_X4(b[np], sBh + addr);
            }
            // Ahi x Bhi
            #pragma unroll
            for (int mf = 0; mf < 2; mf++)
                #pragma unroll
                for (int np = 0; np < 4; np++) {
                    mma16816(acc[mf][np * 2 + 0], ah[mf], b[np][0], b[np][2]);
                    mma16816(acc[mf][np * 2 + 1], ah[mf], b[np][1], b[np][3]);
                }
            // Alo x Bhi
            #pragma unroll
            for (int mf = 0; mf < 2; mf++) {
                int row = wm + mf * 16 + lrow;
                uint32_t addr = (uint32_t)row * 128 + ((uint32_t)(kc ^ (row & 7)) << 4);
                LDSM_X4(al[mf], sAl + addr);
            }
            #pragma unroll
            for (int mf = 0; mf < 2; mf++)
                #pragma unroll
                for (int np = 0; np < 4; np++) {
                    mma16816(acc[mf][np * 2 + 0], al[mf], b[np][0], b[np][2]);
                    mma16816(acc[mf][np * 2 + 1], al[mf], b[np][1], b[np][3]);
                }
            // Ahi x Blo (reload b from Blo)
            #pragma unroll
            for (int np = 0; np < 4; np++) {
                int row = wn + np * 16 + lrow;
                uint32_t addr = (uint32_t)row * 128 + ((uint32_t)(kc ^ (row & 7)) << 4);
                LDSM_X4(b[np], sBl + addr);
            }
            #pragma unroll
            for (int mf = 0; mf < 2; mf++)
                #pragma unroll
                for (int np = 0; np < 4; np++) {
                    mma16816(acc[mf][np * 2 + 0], ah[mf], b[np][0], b[np][2]);
                    mma16816(acc[mf][np * 2 + 1], ah[mf], b[np][1], b[np][3]);
                }
        }
        __syncthreads();
    }

    // ---------------- epilogue ----------------
    const float* bias = conv == 0 ? bq : (conv == 1 ? bk : bv);
    float* outp = cout + (size_t)z * CDIM * SPAT;
    #pragma unroll
    for (int mf = 0; mf < 2; mf++) {
        int m = m0 + wm + mf * 16 + (lane >> 2);
        float bi0 = bias[m], bi1 = bias[m + 8];
        #pragma unroll
        for (int nf = 0; nf < 8; nf++) {
            int n = n0 + wn + ((nf >> 1) << 4) + ((nf & 1) << 3) + (lane & 3) * 2;
            float2 v0 = {acc[mf][nf][0] + bi0, acc[mf][nf][1] + bi0};
            float2 v1 = {acc[mf][nf][2] + bi1, acc[mf][nf][3] + bi1};
            *(float2*)(outp + (size_t)m * SPAT + n) = v0;
            *(float2*)(outp + (size_t)(m + 8) * SPAT + n) = v1;
        }
    }
}

// ---------------- S = scale * Q K^T, masked (FFMA) -------------------------
__global__ __launch_bounds__(256, 2)
void attn_qk(const float* __restrict__ qc, const float* __restrict__ kc,
             const int* __restrict__ mask, float* __restrict__ S) {
    __shared__ float Qs[16][128];
    __shared__ float Ks[16][128];
    const int bh = blockIdx.z;
    const int b = bh >> 4;
    const int t0 = blockIdx.y * 128;
    const int s0 = blockIdx.x * 128;
    const int tid = threadIdx.x;
    const int ty = tid >> 4, tx = tid & 15;
    const int h = bh & 15;

    const float* qp = qc + (size_t)b * CDIM * SPAT + h * HD;
    const float* kp = kc + (size_t)b * CDIM * SPAT + h * HD;
    const int th = tid >> 1;
    const int kq = (tid & 1) * 8;

    float acc[8][8];
    #pragma unroll
    for (int i = 0; i < 8; i++)
        #pragma unroll
        for (int j = 0; j < 8; j++) acc[i][j] = 0.f;

    for (int kk = 0; kk < HD; kk += 16) {
        float4 q0 = *(const float4*)(qp + (size_t)(t0 + th) * SPAT + kk + kq);
        float4 q1 = *(const float4*)(qp + (size_t)(t0 + th) * SPAT + kk + kq + 4);
        Qs[kq + 0][th] = q0.x; Qs[kq + 1][th] = q0.y; Qs[kq + 2][th] = q0.z; Qs[kq + 3][th] = q0.w;
        Qs[kq + 4][th] = q1.x; Qs[kq + 5][th] = q1.y; Qs[kq + 6][th] = q1.z; Qs[kq + 7][th] = q1.w;
        float4 k0 = *(const float4*)(kp + (size_t)(s0 + th) * SPAT + kk + kq);
        float4 k1 = *(const float4*)(kp + (size_t)(s0 + th) * SPAT + kk + kq + 4);
        Ks[kq + 0][th] = k0.x; Ks[kq + 1][th] = k0.y; Ks[kq + 2][th] = k0.z; Ks[kq + 3][th] = k0.w;
        Ks[kq + 4][th] = k1.x; Ks[kq + 5][th] = k1.y; Ks[kq + 6][th] = k1.z; Ks[kq + 7][th] = k1.w;
        __syncthreads();
        #pragma unroll
        for (int k = 0; k < 16; k++) {
            float4 a0 = *(const float4*)&Qs[k][ty * 8];
            float4 a1 = *(const float4*)&Qs[k][ty * 8 + 4];
            float4 b0 = *(const float4*)&Ks[k][tx * 8];
            float4 b1 = *(const float4*)&Ks[k][tx * 8 + 4];
            float av[8] = {a0.x, a0.y, a0.z, a0.w, a1.x, a1.y, a1.z, a1.w};
            float bvv[8] = {b0.x, b0.y, b0.z, b0.w, b1.x, b1.y, b1.z, b1.w};
            #pragma unroll
            for (int i = 0; i < 8; i++)
                #pragma unroll
                for (int j = 0; j < 8; j++)
                    acc[i][j] += av[i] * bvv[j];
        }
        __syncthreads();
    }

    float* Srow = S + (size_t)bh * CDIM * CDIM;
    const int* mrow = mask + (size_t)b * CDIM * CDIM;
    #pragma unroll
    for (int i = 0; i < 8; i++) {
        int t = t0 + ty * 8 + i;
        #pragma unroll
        for (int j = 0; j < 8; j++) {
            int s = s0 + tx * 8 + j;
            int mv = mrow[(size_t)t * CDIM + s];
            Srow[(size_t)t * CDIM + s] = mv ? acc[i][j] * 0.125f : -1e9f;
        }
    }
}

// ---------------- row softmax ----------------------------------------------
__global__ __launch_bounds__(256)
void softmax_rows(float* __restrict__ S) {
    __shared__ float red[8];
    const int t = threadIdx.x;
    float4* p = (float4*)(S + (size_t)blockIdx.x * 1024);
    float4 v = p[t];
    float m = fmaxf(fmaxf(v.x, v.y), fmaxf(v.z, v.w));
    #pragma unroll
    for (int o = 16; o > 0; o >>= 1) m = fmaxf(m, __shfl_xor_sync(0xffffffffu, m, o));
    if ((t & 31) == 0) red[t >> 5] = m;
    __syncthreads();
    m = red[0];
    #pragma unroll
    for (int i = 1; i < 8; i++) m = fmaxf(m, red[i]);
    __syncthreads();
    v.x = __expf(v.x - m); v.y = __expf(v.y - m);
    v.z = __expf(v.z - m); v.w = __expf(v.w - m);
    float s = v.x + v.y + v.z + v.w;
    #pragma unroll
    for (int o = 16; o > 0; o >>= 1) s += __shfl_xor_sync(0xffffffffu, s, o);
    if ((t & 31) == 0) red[t >> 5] = s;
    __syncthreads();
    s = red[0];
    #pragma unroll
    for (int i = 1; i < 8; i++) s += red[i];
    float r = 1.0f / s;
    v.x *= r; v.y *= r; v.z *= r; v.w *= r;
    p[t] = v;
}

// ---------------- O = P V ---------------------------------------------------
__global__ __launch_bounds__(256, 2)
void attn_pv(const float* __restrict__ P, const float* __restrict__ vc,
             float* __restrict__ ao) {
    __shared__ float Ps[16][128];
    __shared__ float Vs[16][64];
    const int bh = blockIdx.z;
    const int b = bh >> 4, h = bh & 15;
    const int t0 = blockIdx.y * 128;
    const int tid = threadIdx.x;
    const int ty = tid >> 4, tx = tid & 15;

    const float* Pp = P + (size_t)bh * CDIM * CDIM;
    const float* vp = vc + (size_t)b * CDIM * SPAT + h * HD;

    float acc[8][4];
    #pragma unroll
    for (int i = 0; i < 8; i++)
        #pragma unroll
        for (int j = 0; j < 4; j++) acc[i][j] = 0.f;

    const int th = tid >> 1;
    const int kq = (tid & 1) * 8;
    const int vk = tid >> 4;
    const int vj = (tid & 15) * 4;

    for (int kk = 0; kk < CDIM; kk += 16) {
        float4 p0 = *(const float4*)(Pp + (size_t)(t0 + th) * CDIM + kk + kq);
        float4 p1 = *(const float4*)(Pp + (size_t)(t0 + th) * CDIM + kk + kq + 4);
        Ps[kq + 0][th] = p0.x; Ps[kq + 1][th] = p0.y; Ps[kq + 2][th] = p0.z; Ps[kq + 3][th] = p0.w;
        Ps[kq + 4][th] = p1.x; Ps[kq + 5][th] = p1.y; Ps[kq + 6][th] = p1.z; Ps[kq + 7][th] = p1.w;
        *(float4*)&Vs[vk][vj] = *(const float4*)(vp + (size_t)(kk + vk) * SPAT + vj);
        __syncthreads();
        #pragma unroll
        for (int k = 0; k < 16; k++) {
            float4 bvv = *(const float4*)&Vs[k][tx * 4];
            float4 a0 = *(const float4*)&Ps[k][ty * 8];
            float4 a1 = *(const float4*)&Ps[k][ty * 8 + 4];
            float av[8] = {a0.x, a0.y, a0.z, a0.w, a1.x, a1.y, a1.z, a1.w};
            #pragma unroll
            for (int i = 0; i < 8; i++) {
                acc[i][0] += av[i] * bvv.x;
                acc[i][1] += av[i] * bvv.y;
                acc[i][2] += av[i] * bvv.z;
                acc[i][3] += av[i] * bvv.w;
            }
        }
        __syncthreads();
    }

    float* aop = ao + (size_t)b * CDIM * SPAT + h * HD;
    #pragma unroll
    for (int i = 0; i < 8; i++) {
        int t = t0 + ty * 8 + i;
        float4 o0 = {acc[i][0], acc[i][1], acc[i][2], acc[i][3]};
        *(float4*)(aop + (size_t)t * SPAT + tx * 4) = o0;
    }
}

// ---------------- output projection -----------------------------------------
__global__ __launch_bounds__(256, 2)
void proj_gemm(const float* __restrict__ A, const float* __restrict__ Wo,
               const float* __restrict__ bo, float* __restrict__ out) {
    __shared__ float As[8][128];
    __shared__ float Bs[8][128];
    const int row0 = blockIdx.y * 128;
    const int m0 = blockIdx.x * 128;
    const int tid = threadIdx.x;
    const int ty = tid >> 4, tx = tid & 15;
    const int th = tid >> 1;
    const int kq = (tid & 1) * 4;

    float acc[8][8];
    #pragma unroll
    for (int i = 0; i < 8; i++)
        #pragma unroll
        for (int j = 0; j < 8; j++) acc[i][j] = 0.f;

    for (int kk = 0; kk < 1024; kk += 8) {
        float4 a = *(const float4*)(A + (size_t)(row0 + th) * 1024 + kk + kq);
        As[kq + 0][th] = a.x; As[kq + 1][th] = a.y; As[kq + 2][th] = a.z; As[kq + 3][th] = a.w;
        float4 w = *(const float4*)(Wo + (size_t)(m0 + th) * 1024 + kk + kq);
        Bs[kq + 0][th] = w.x; Bs[kq + 1][th] = w.y; Bs[kq + 2][th] = w.z; Bs[kq + 3][th] = w.w;
        __syncthreads();
        #pragma unroll
        for (int k = 0; k < 8; k++) {
            float4 a0 = *(const float4*)&As[k][ty * 8];
            float4 a1 = *(const float4*)&As[k][ty * 8 + 4];
            float4 b0 = *(const float4*)&Bs[k][tx * 8];
            float4 b1 = *(const float4*)&Bs[k][tx * 8 + 4];
            float av[8] = {a0.x, a0.y, a0.z, a0.w, a1.x, a1.y, a1.z, a1.w};
            float bvv[8] = {b0.x, b0.y, b0.z, b0.w, b1.x, b1.y, b1.z, b1.w};
            #pragma unroll
            for (int i = 0; i < 8; i++)
                #pragma unroll
                for (int j = 0; j < 8; j++)
                    acc[i][j] += av[i] * bvv[j];
        }
        __syncthreads();
    }

    #pragma unroll
    for (int i = 0; i < 8; i++) {
        int rr = row0 + ty * 8 + i;
        float* op = out + (size_t)rr * 1024 + m0 + tx * 8;
        float4 o0 = {acc[i][0] + bo[m0 + tx * 8 + 0], acc[i][1] + bo[m0 + tx * 8 + 1],
                     acc[i][2] + bo[m0 + tx * 8 + 2], acc[i][3] + bo[m0 + tx * 8 + 3]};
        float4 o1 = {acc[i][4] + bo[m0 + tx * 8 + 4], acc[i][5] + bo[m0 + tx * 8 + 5],
                     acc[i][6] + bo[m0 + tx * 8 + 6], acc[i][7] + bo[m0 + tx * 8 + 7]};
        *(float4*)op = o0;
        *(float4*)(op + 4) = o1;
    }
}

// ---------------- launch ---------------------------------------------------
extern "C" void kernel_launch(void* const* d_in, const int* in_sizes, int n_in,
                              void* d_out, int out_size) {
    const float* q  = (const float*)d_in[0];
    const float* k  = (const float*)d_in[1];
    const float* v  = (const float*)d_in[2];
    const float* Wq = (const float*)d_in[3];
    const float* bq = (const float*)d_in[4];
    const float* Wk = (const float*)d_in[5];
    const float* bk = (const float*)d_in[6];
    const float* Wv = (const float*)d_in[7];
    const float* bv = (const float*)d_in[8];
    const float* Wo = (const float*)d_in[9];
    const float* bo = (const float*)d_in[10];
    const int*   mask = (const int*)d_in[11];
    float* out = (float*)d_out;

    __nv_bfloat16 *whi, *wlo, *ihi, *ilo;
    float *cout, *ao, *attn;
    cudaGetSymbolAddress((void**)&whi, g_whi);
    cudaGetSymbolAddress((void**)&wlo, g_wlo);
    cudaGetSymbolAddress((void**)&ihi, g_ihi);
    cudaGetSymbolAddress((void**)&ilo, g_ilo);
    cudaGetSymbolAddress((void**)&cout, g_cout);
    cudaGetSymbolAddress((void**)&ao, g_ao);
    cudaGetSymbolAddress((void**)&attn, g_attn);

    cudaFuncSetAttribute(conv_mma, cudaFuncAttributeMaxDynamicSharedMemorySize, CM_SMEM);

    split_w<<<dim3(CDIM, 3), 256>>>(Wq, Wk, Wv, whi, wlo);
    transpose_split_in<<<dim3(32, 32, 24), dim3(32, 8)>>>(q, k, v, ihi, ilo);

    conv_mma<<<dim3(8, 8, 24), 256, CM_SMEM>>>(whi, wlo, ihi, ilo, bq, bk, bv, cout);

    const float* qc = cout;
    const float* kc = cout + (size_t)8 * CDIM * SPAT;
    const float* vc = cout + (size_t)16 * CDIM * SPAT;

    attn_qk<<<dim3(8, 8, BATCH * NH), 256>>>(qc, kc, mask, attn);
    softmax_rows<<<BATCH * NH * CDIM, 256>>>(attn);
    attn_pv<<<dim3(1, 8, BATCH * NH), 256>>>(attn, vc, ao);

    proj_gemm<<<dim3(8, 64), 256>>>(ao, Wo, bo, out);
}

// round 4
// speedup vs baseline: 3.2692x; 1.1803x over previous
#include <cuda_runtime.h>
#include <cuda_bf16.h>
#include <cstdint>
#include <math.h>

// Shapes
#define BATCH 8
#define CDIM  1024      // channels == tokens
#define SPAT  1024      // 32*32 spatial
#define NH    16
#define HD    64
#define CONVK 9216      // 1024*9

// ---------------- scratch (device globals) ---------------------------------
__device__ __nv_bfloat16 g_whi[(size_t)3 * CDIM * CONVK];   // [conv][o][r*1024+i]
__device__ __nv_bfloat16 g_wlo[(size_t)3 * CDIM * CONVK];
__device__ __nv_bfloat16 g_ihi[(size_t)24 * SPAT * CDIM];   // [conv*8+b][pix][i]
__device__ __nv_bfloat16 g_ilo[(size_t)24 * SPAT * CDIM];
__device__ __nv_bfloat16 g_chi[(size_t)24 * CDIM * SPAT];   // conv out hi [z][o][pix]
__device__ __nv_bfloat16 g_clo[(size_t)24 * CDIM * SPAT];
__device__ __nv_bfloat16 g_vthi[(size_t)BATCH * SPAT * CDIM]; // V^T [b][d][s]
__device__ __nv_bfloat16 g_vtlo[(size_t)BATCH * SPAT * CDIM];
__device__ __nv_bfloat16 g_wohi[(size_t)CDIM * CDIM];
__device__ __nv_bfloat16 g_wolo[(size_t)CDIM * CDIM];
__device__ __nv_bfloat16 g_phi[(size_t)BATCH * NH * CDIM * CDIM];  // P hi
__device__ __nv_bfloat16 g_plo[(size_t)BATCH * NH * CDIM * CDIM];
__device__ __nv_bfloat16 g_aohi[(size_t)BATCH * CDIM * SPAT];
__device__ __nv_bfloat16 g_aolo[(size_t)BATCH * CDIM * SPAT];
__device__ float g_attn[(size_t)BATCH * NH * CDIM * CDIM];  // S fp32 (512MB)

// ---------------- PTX helpers (sm_80-baseline only) ------------------------
__device__ __forceinline__ uint32_t smem_u32(const void* p) {
    uint32_t a;
    asm("{ .reg .u64 t; cvta.to.shared.u64 t, %1; cvt.u32.u64 %0, t; }" : "=r"(a) : "l"(p));
    return a;
}
__device__ __forceinline__ void cp_async16(uint32_t dst, const void* src, int src_bytes) {
    asm volatile("cp.async.cg.shared.global [%0], [%1], 16, %2;"
                 :: "r"(dst), "l"(src), "r"(src_bytes) : "memory");
}
#define CP_COMMIT() asm volatile("cp.async.commit_group;" ::: "memory")
#define CP_WAIT(n)  asm volatile("cp.async.wait_group %0;" :: "n"(n) : "memory")

#define LDSM_X4(r, a) \
    asm volatile("ldmatrix.sync.aligned.m8n8.x4.shared.b16 {%0,%1,%2,%3}, [%4];" \
                 : "=r"((r)[0]), "=r"((r)[1]), "=r"((r)[2]), "=r"((r)[3]) : "r"(a))

__device__ __forceinline__ void mma16816(float* c, const uint32_t* a, uint32_t b0, uint32_t b1) {
    asm volatile("mma.sync.aligned.m16n8k16.row.col.f32.bf16.bf16.f32 "
                 "{%0,%1,%2,%3},{%4,%5,%6,%7},{%8,%9},{%0,%1,%2,%3};"
                 : "+f"(c[0]), "+f"(c[1]), "+f"(c[2]), "+f"(c[3])
                 : "r"(a[0]), "r"(a[1]), "r"(a[2]), "r"(a[3]), "r"(b0), "r"(b1));
}

__device__ __forceinline__ void split_store2(__nv_bfloat16* hi, __nv_bfloat16* lo,
                                             size_t idx, float a, float b) {
    __nv_bfloat16 ha = __float2bfloat16(a), hb = __float2bfloat16(b);
    __nv_bfloat162 hv; hv.x = ha; hv.y = hb;
    *(__nv_bfloat162*)(hi + idx) = hv;
    __nv_bfloat162 lv;
    lv.x = __float2bfloat16(a - __bfloat162float(ha));
    lv.y = __float2bfloat16(b - __bfloat162float(hb));
    *(__nv_bfloat162*)(lo + idx) = lv;
}

// ---------------- precompute: weight split to [o][r*1024+i] ----------------
__global__ void split_w(const float* __restrict__ Wq, const float* __restrict__ Wk,
                        const float* __restrict__ Wv,
                        __nv_bfloat16* __restrict__ hi, __nv_bfloat16* __restrict__ lo) {
    const int o = blockIdx.x, conv = blockIdx.y;
    const float* W = (conv == 0 ? Wq : (conv == 1 ? Wk : Wv)) + (size_t)o * CONVK;
    size_t ob = ((size_t)conv * CDIM + o) * CONVK;
    for (int kk = threadIdx.x; kk < CONVK; kk += 256) {
        int r = kk >> 10, i = kk & 1023;
        float w = W[i * 9 + r];
        __nv_bfloat16 h = __float2bfloat16(w);
        hi[ob + kk] = h;
        lo[ob + kk] = __float2bfloat16(w - __bfloat162float(h));
    }
}

__global__ void split_wo(const float* __restrict__ Wo,
                         __nv_bfloat16* __restrict__ hi, __nv_bfloat16* __restrict__ lo) {
    int idx = blockIdx.x * 256 + threadIdx.x;
    float w = Wo[idx];
    __nv_bfloat16 h = __float2bfloat16(w);
    hi[idx] = h;
    lo[idx] = __float2bfloat16(w - __bfloat162float(h));
}

// ---------------- precompute: transpose + split inputs ---------------------
__global__ void transpose_split_in(const float* __restrict__ q, const float* __restrict__ k,
                                   const float* __restrict__ v,
                                   __nv_bfloat16* __restrict__ hi, __nv_bfloat16* __restrict__ lo) {
    __shared__ float t[32][33];
    const int z = blockIdx.z, conv = z >> 3, b = z & 7;
    const float* src = (conv == 0 ? q : (conv == 1 ? k : v)) + (size_t)b * CDIM * SPAT;
    const int i0 = blockIdx.y * 32, p0 = blockIdx.x * 32;
    const int tx = threadIdx.x, ty = threadIdx.y;
    #pragma unroll
    for (int r = ty; r < 32; r += 8) t[r][tx] = src[(size_t)(i0 + r) * SPAT + p0 + tx];
    __syncthreads();
    size_t base = (size_t)z * SPAT * CDIM;
    #pragma unroll
    for (int r = ty; r < 32; r += 8) {
        float w = t[tx][r];
        __nv_bfloat16 h = __float2bfloat16(w);
        size_t idx = base + (size_t)(p0 + r) * CDIM + i0 + tx;
        hi[idx] = h;
        lo[idx] = __float2bfloat16(w - __bfloat162float(h));
    }
}

// ---------------- bf16 transpose (V -> V^T) --------------------------------
__global__ void tr_bf16(const __nv_bfloat16* __restrict__ in, __nv_bfloat16* __restrict__ out) {
    __shared__ __nv_bfloat16 t[32][33];
    const int b = blockIdx.z, s0 = blockIdx.y * 32, d0 = blockIdx.x * 32;
    const __nv_bfloat16* ip = in + (size_t)b * CDIM * SPAT;
    __nv_bfloat16* op = out + (size_t)b * CDIM * SPAT;
    const int tx = threadIdx.x, ty = threadIdx.y;
    #pragma unroll
    for (int r = ty; r < 32; r += 8) t[r][tx] = ip[(size_t)(s0 + r) * SPAT + d0 + tx];
    __syncthreads();
    #pragma unroll
    for (int r = ty; r < 32; r += 8) op[(size_t)(d0 + r) * CDIM + s0 + tx] = t[tx][r];
}

// ---------------- conv via warp MMA, 2-stage pipeline ----------------------
#define CONV_STAGE 65536
#define CM_NIT  144

__global__ __launch_bounds__(256)
void conv_mma(const __nv_bfloat16* __restrict__ whi, const __nv_bfloat16* __restrict__ wlo,
              const __nv_bfloat16* __restrict__ ihi, const __nv_bfloat16* __restrict__ ilo,
              const float* __restrict__ bq, const float* __restrict__ bk,
              const float* __restrict__ bv,
              __nv_bfloat16* __restrict__ chi, __nv_bfloat16* __restrict__ clo) {
    extern __shared__ char smem[];
    const uint32_t sb = smem_u32(smem);
    const int tid = threadIdx.x, wid = tid >> 5, lane = tid & 31;
    const int z = blockIdx.z, conv = z >> 3;
    const int m0 = blockIdx.y * 128, n0 = blockIdx.x * 128;

    const __nv_bfloat16* Ah = whi + ((size_t)conv * CDIM + m0) * CONVK;
    const __nv_bfloat16* Al = wlo + ((size_t)conv * CDIM + m0) * CONVK;
    const __nv_bfloat16* Ih = ihi + (size_t)z * SPAT * CDIM;
    const __nv_bfloat16* Il = ilo + (size_t)z * SPAT * CDIM;

    const int wm = (wid & 3) * 32, wn = (wid >> 2) * 64;
    const int lrow = lane & 15, lkc = lane >> 4;

    float acc[2][8][4];
    #pragma unroll
    for (int i = 0; i < 2; i++)
        #pragma unroll
        for (int j = 0; j < 8; j++)
            #pragma unroll
            for (int q = 0; q < 4; q++) acc[i][j][q] = 0.f;

    auto load_stage = [&](int s, int it) {
        uint32_t base = sb + s * CONV_STAGE;
        const int r = it >> 4;
        const int dy = r / 3 - 1, dx = r % 3 - 1;
        const int i0 = (it & 15) << 6;
        #pragma unroll
        for (int p = 0; p < 4; p++) {
            int ci = tid + p * 256;
            int row = ci >> 3, c = ci & 7;
            uint32_t off = (uint32_t)row * 128 + ((uint32_t)(c ^ (row & 7)) << 4);
            cp_async16(base + off, Ah + (size_t)row * CONVK + it * 64 + c * 8, 16);
            cp_async16(base + 16384 + off, Al + (size_t)row * CONVK + it * 64 + c * 8, 16);
            int pix = n0 + row;
            int y = (pix >> 5) + dy, x = (pix & 31) + dx;
            bool ok = ((unsigned)y < 32u) && ((unsigned)x < 32u);
            int sp = ok ? (y * 32 + x) : 0;
            int nb = ok ? 16 : 0;
            cp_async16(base + 32768 + off, Ih + (size_t)sp * CDIM + i0 + c * 8, nb);
            cp_async16(base + 49152 + off, Il + (size_t)sp * CDIM + i0 + c * 8, nb);
        }
        CP_COMMIT();
    };

    load_stage(0, 0);

    for (int it = 0; it < CM_NIT; it++) {
        int s = it & 1;
        if (it + 1 < CM_NIT) { load_stage(s ^ 1, it + 1); CP_WAIT(1); }
        else                 { CP_WAIT(0); }
        __syncthreads();

        const uint32_t sAh = sb + s * CONV_STAGE;
        const uint32_t sAl = sAh + 16384, sBh = sAh + 32768, sBl = sAh + 49152;
        #pragma unroll
        for (int ks = 0; ks < 4; ks++) {
            const int kc = ks * 2 + lkc;
            uint32_t ah[2][4], al[2][4], bfr[4][4];
            #pragma unroll
            for (int mf = 0; mf < 2; mf++) {
                int row = wm + mf * 16 + lrow;
                LDSM_X4(ah[mf], sAh + (uint32_t)row * 128 + ((uint32_t)(kc ^ (row & 7)) << 4));
            }
            #pragma unroll
            for (int np = 0; np < 4; np++) {
                int row = wn + np * 16 + lrow;
                LDSM_X4(bfr[np], sBh + (uint32_t)row * 128 + ((uint32_t)(kc ^ (row & 7)) << 4));
            }
            #pragma unroll
            for (int mf = 0; mf < 2; mf++)
                #pragma unroll
                for (int np = 0; np < 4; np++) {
                    mma16816(acc[mf][np * 2 + 0], ah[mf], bfr[np][0], bfr[np][2]);
                    mma16816(acc[mf][np * 2 + 1], ah[mf], bfr[np][1], bfr[np][3]);
                }
            #pragma unroll
            for (int mf = 0; mf < 2; mf++) {
                int row = wm + mf * 16 + lrow;
                LDSM_X4(al[mf], sAl + (uint32_t)row * 128 + ((uint32_t)(kc ^ (row & 7)) << 4));
            }
            #pragma unroll
            for (int mf = 0; mf < 2; mf++)
                #pragma unroll
                for (int np = 0; np < 4; np++) {
                    mma16816(acc[mf][np * 2 + 0], al[mf], bfr[np][0], bfr[np][2]);
                    mma16816(acc[mf][np * 2 + 1], al[mf], bfr[np][1], bfr[np][3]);
                }
            #pragma unroll
            for (int np = 0; np < 4; np++) {
                int row = wn + np * 16 + lrow;
                LDSM_X4(bfr[np], sBl + (uint32_t)row * 128 + ((uint32_t)(kc ^ (row & 7)) << 4));
            }
            #pragma unroll
            for (int mf = 0; mf < 2; mf++)
                #pragma unroll
                for (int np = 0; np < 4; np++) {
                    mma16816(acc[mf][np * 2 + 0], ah[mf], bfr[np][0], bfr[np][2]);
                    mma16816(acc[mf][np * 2 + 1], ah[mf], bfr[np][1], bfr[np][3]);
                }
        }
        __syncthreads();
    }

    const float* bias = conv == 0 ? bq : (conv == 1 ? bk : bv);
    __nv_bfloat16* oh = chi + (size_t)z * CDIM * SPAT;
    __nv_bfloat16* ol = clo + (size_t)z * CDIM * SPAT;
    #pragma unroll
    for (int mf = 0; mf < 2; mf++) {
        int m = m0 + wm + mf * 16 + (lane >> 2);
        float bi0 = bias[m], bi1 = bias[m + 8];
        #pragma unroll
        for (int nf = 0; nf < 8; nf++) {
            int n = n0 + wn + ((nf >> 1) << 4) + ((nf & 1) << 3) + (lane & 3) * 2;
            split_store2(oh, ol, (size_t)m * SPAT + n, acc[mf][nf][0] + bi0, acc[mf][nf][1] + bi0);
            split_store2(oh, ol, (size_t)(m + 8) * SPAT + n, acc[mf][nf][2] + bi1, acc[mf][nf][3] + bi1);
        }
    }
}

// ---------------- QK^T via MMA (K=64 single shot) --------------------------
__global__ __launch_bounds__(256)
void qk_mma(const __nv_bfloat16* __restrict__ chi, const __nv_bfloat16* __restrict__ clo,
            const int* __restrict__ mask, float* __restrict__ S) {
    extern __shared__ char smem[];
    const uint32_t sb = smem_u32(smem);
    const int tid = threadIdx.x, wid = tid >> 5, lane = tid & 31;
    const int bh = blockIdx.z, b = bh >> 4, h = bh & 15;
    const int t0 = blockIdx.y * 128, s0 = blockIdx.x * 128;

    const __nv_bfloat16* Qh = chi + (size_t)b * CDIM * SPAT + h * HD;
    const __nv_bfloat16* Ql = clo + (size_t)b * CDIM * SPAT + h * HD;
    const __nv_bfloat16* Kh = chi + (size_t)(8 + b) * CDIM * SPAT + h * HD;
    const __nv_bfloat16* Kl = clo + (size_t)(8 + b) * CDIM * SPAT + h * HD;

    const uint32_t sAh = sb, sAl = sb + 16384, sBh = sb + 32768, sBl = sb + 49152;
    #pragma unroll
    for (int p = 0; p < 4; p++) {
        int ci = tid + p * 256;
        int row = ci >> 3, c = ci & 7;
        uint32_t off = (uint32_t)row * 128 + ((uint32_t)(c ^ (row & 7)) << 4);
        cp_async16(sAh + off, Qh + (size_t)(t0 + row) * SPAT + c * 8, 16);
        cp_async16(sAl + off, Ql + (size_t)(t0 + row) * SPAT + c * 8, 16);
        cp_async16(sBh + off, Kh + (size_t)(s0 + row) * SPAT + c * 8, 16);
        cp_async16(sBl + off, Kl + (size_t)(s0 + row) * SPAT + c * 8, 16);
    }
    CP_COMMIT();
    CP_WAIT(0);
    __syncthreads();

    const int wm = (wid & 3) * 32, wn = (wid >> 2) * 64;
    const int lrow = lane & 15, lkc = lane >> 4;

    float acc[2][8][4];
    #pragma unroll
    for (int i = 0; i < 2; i++)
        #pragma unroll
        for (int j = 0; j < 8; j++)
            #pragma unroll
            for (int q = 0; q < 4; q++) acc[i][j][q] = 0.f;

    #pragma unroll
    for (int ks = 0; ks < 4; ks++) {
        const int kc = ks * 2 + lkc;
        uint32_t ah[2][4], al[2][4], bfr[4][4];
        #pragma unroll
        for (int mf = 0; mf < 2; mf++) {
            int row = wm + mf * 16 + lrow;
            LDSM_X4(ah[mf], sAh + (uint32_t)row * 128 + ((uint32_t)(kc ^ (row & 7)) << 4));
        }
        #pragma unroll
        for (int np = 0; np < 4; np++) {
            int row = wn + np * 16 + lrow;
            LDSM_X4(bfr[np], sBh + (uint32_t)row * 128 + ((uint32_t)(kc ^ (row & 7)) << 4));
        }
        #pragma unroll
        for (int mf = 0; mf < 2; mf++)
            #pragma unroll
            for (int np = 0; np < 4; np++) {
                mma16816(acc[mf][np * 2 + 0], ah[mf], bfr[np][0], bfr[np][2]);
                mma16816(acc[mf][np * 2 + 1], ah[mf], bfr[np][1], bfr[np][3]);
            }
        #pragma unroll
        for (int mf = 0; mf < 2; mf++) {
            int row = wm + mf * 16 + lrow;
            LDSM_X4(al[mf], sAl + (uint32_t)row * 128 + ((uint32_t)(kc ^ (row & 7)) << 4));
        }
        #pragma unroll
        for (int mf = 0; mf < 2; mf++)
            #pragma unroll
            for (int np = 0; np < 4; np++) {
                mma16816(acc[mf][np * 2 + 0], al[mf], bfr[np][0], bfr[np][2]);
                mma16816(acc[mf][np * 2 + 1], al[mf], bfr[np][1], bfr[np][3]);
            }
        #pragma unroll
        for (int np = 0; np < 4; np++) {
            int row = wn + np * 16 + lrow;
            LDSM_X4(bfr[np], sBl + (uint32_t)row * 128 + ((uint32_t)(kc ^ (row & 7)) << 4));
        }
        #pragma unroll
        for (int mf = 0; mf < 2; mf++)
            #pragma unroll
            for (int np = 0; np < 4; np++) {
                mma16816(acc[mf][np * 2 + 0], ah[mf], bfr[np][0], bfr[np][2]);
                mma16816(acc[mf][np * 2 + 1], ah[mf], bfr[np][1], bfr[np][3]);
            }
    }

    float* Srow = S + (size_t)bh * CDIM * CDIM;
    const int* mrow = mask + (size_t)b * CDIM * CDIM;
    #pragma unroll
    for (int mf = 0; mf < 2; mf++) {
        int t = t0 + wm + mf * 16 + (lane >> 2);
        #pragma unroll
        for (int nf = 0; nf < 8; nf++) {
            int n = s0 + wn + ((nf >> 1) << 4) + ((nf & 1) << 3) + (lane & 3) * 2;
            int2 m0v = *(const int2*)(mrow + (size_t)t * CDIM + n);
            int2 m1v = *(const int2*)(mrow + (size_t)(t + 8) * CDIM + n);
            float2 v0 = {m0v.x ? acc[mf][nf][0] * 0.125f : -1e9f,
                         m0v.y ? acc[mf][nf][1] * 0.125f : -1e9f};
            float2 v1 = {m1v.x ? acc[mf][nf][2] * 0.125f : -1e9f,
                         m1v.y ? acc[mf][nf][3] * 0.125f : -1e9f};
            *(float2*)(Srow + (size_t)t * CDIM + n) = v0;
            *(float2*)(Srow + (size_t)(t + 8) * CDIM + n) = v1;
        }
    }
}

// ---------------- row softmax -> P hi/lo bf16 ------------------------------
__global__ __launch_bounds__(256)
void softmax_split(const float* __restrict__ S,
                   __nv_bfloat16* __restrict__ ph, __nv_bfloat16* __restrict__ pl) {
    __shared__ float red[8];
    const int t = threadIdx.x;
    const float4* p = (const float4*)(S + (size_t)blockIdx.x * 1024);
    float4 v = p[t];
    float m = fmaxf(fmaxf(v.x, v.y), fmaxf(v.z, v.w));
    #pragma unroll
    for (int o = 16; o > 0; o >>= 1) m = fmaxf(m, __shfl_xor_sync(0xffffffffu, m, o));
    if ((t & 31) == 0) red[t >> 5] = m;
    __syncthreads();
    m = red[0];
    #pragma unroll
    for (int i = 1; i < 8; i++) m = fmaxf(m, red[i]);
    __syncthreads();
    v.x = __expf(v.x - m); v.y = __expf(v.y - m);
    v.z = __expf(v.z - m); v.w = __expf(v.w - m);
    float s = v.x + v.y + v.z + v.w;
    #pragma unroll
    for (int o = 16; o > 0; o >>= 1) s += __shfl_xor_sync(0xffffffffu, s, o);
    if ((t & 31) == 0) red[t >> 5] = s;
    __syncthreads();
    s = red[0];
    #pragma unroll
    for (int i = 1; i < 8; i++) s += red[i];
    float r = 1.0f / s;
    v.x *= r; v.y *= r; v.z *= r; v.w *= r;
    size_t base = (size_t)blockIdx.x * 1024 + t * 4;
    split_store2(ph, pl, base, v.x, v.y);
    split_store2(ph, pl, base + 2, v.z, v.w);
}

// ---------------- O = P V via MMA, 2-stage pipeline ------------------------
#define PV_STAGE 49152
__global__ __launch_bounds__(256)
void pv_mma(const __nv_bfloat16* __restrict__ phi, const __nv_bfloat16* __restrict__ plo,
            const __nv_bfloat16* __restrict__ vthi, const __nv_bfloat16* __restrict__ vtlo,
            __nv_bfloat16* __restrict__ aoh, __nv_bfloat16* __restrict__ aol) {
    extern __shared__ char smem[];
    const uint32_t sb = smem_u32(smem);
    const int tid = threadIdx.x, wid = tid >> 5, lane = tid & 31;
    const int bh = blockIdx.z, b = bh >> 4, h = bh & 15;
    const int t0 = blockIdx.x * 128;

    const __nv_bfloat16* Ph = phi + (size_t)bh * CDIM * CDIM + (size_t)t0 * CDIM;
    const __nv_bfloat16* Pl = plo + (size_t)bh * CDIM * CDIM + (size_t)t0 * CDIM;
    const __nv_bfloat16* Vh = vthi + (size_t)b * SPAT * CDIM + (size_t)(h * HD) * CDIM;
    const __nv_bfloat16* Vl = vtlo + (size_t)b * SPAT * CDIM + (size_t)(h * HD) * CDIM;

    const int wm = (wid & 3) * 32, wn = (wid >> 2) * 32;
    const int lrow = lane & 15, lkc = lane >> 4;

    float acc[2][4][4];
    #pragma unroll
    for (int i = 0; i < 2; i++)
        #pragma unroll
        for (int j = 0; j < 4; j++)
            #pragma unroll
            for (int q = 0; q < 4; q++) acc[i][j][q] = 0.f;

    auto load_stage = [&](int s, int it) {
        uint32_t base = sb + s * PV_STAGE;
        #pragma unroll
        for (int p = 0; p < 4; p++) {
            int ci = tid + p * 256;
            int row = ci >> 3, c = ci & 7;
            uint32_t off = (uint32_t)row * 128 + ((uint32_t)(c ^ (row & 7)) << 4);
            cp_async16(base + off, Ph + (size_t)row * CDIM + it * 64 + c * 8, 16);
            cp_async16(base + 16384 + off, Pl + (size_t)row * CDIM + it * 64 + c * 8, 16);
        }
        #pragma unroll
        for (int p = 0; p < 2; p++) {
            int ci = tid + p * 256;
            int row = ci >> 3, c = ci & 7;
            uint32_t off = (uint32_t)row * 128 + ((uint32_t)(c ^ (row & 7)) << 4);
            cp_async16(base + 32768 + off, Vh + (size_t)row * CDIM + it * 64 + c * 8, 16);
            cp_async16(base + 40960 + off, Vl + (size_t)row * CDIM + it * 64 + c * 8, 16);
        }
        CP_COMMIT();
    };

    load_stage(0, 0);
    for (int it = 0; it < 16; it++) {
        int s = it & 1;
        if (it + 1 < 16) { load_stage(s ^ 1, it + 1); CP_WAIT(1); }
        else             { CP_WAIT(0); }
        __syncthreads();

        const uint32_t sAh = sb + s * PV_STAGE;
        const uint32_t sAl = sAh + 16384, sBh = sAh + 32768, sBl = sAh + 40960;
        #pragma unroll
        for (int ks = 0; ks < 4; ks++) {
            const int kc = ks * 2 + lkc;
            uint32_t ah[2][4], al[2][4], bfr[2][4];
            #pragma unroll
            for (int mf = 0; mf < 2; mf++) {
                int row = wm + mf * 16 + lrow;
                LDSM_X4(ah[mf], sAh + (uint32_t)row * 128 + ((uint32_t)(kc ^ (row & 7)) << 4));
            }
            #pragma unroll
            for (int np = 0; np < 2; np++) {
                int row = wn + np * 16 + lrow;
                LDSM_X4(bfr[np], sBh + (uint32_t)row * 128 + ((uint32_t)(kc ^ (row & 7)) << 4));
            }
            #pragma unroll
            for (int mf = 0; mf < 2; mf++)
                #pragma unroll
                for (int np = 0; np < 2; np++) {
                    mma16816(acc[mf][np * 2 + 0], ah[mf], bfr[np][0], bfr[np][2]);
                    mma16816(acc[mf][np * 2 + 1], ah[mf], bfr[np][1], bfr[np][3]);
                }
            #pragma unroll
            for (int mf = 0; mf < 2; mf++) {
                int row = wm + mf * 16 + lrow;
                LDSM_X4(al[mf], sAl + (uint32_t)row * 128 + ((uint32_t)(kc ^ (row & 7)) << 4));
            }
            #pragma unroll
            for (int mf = 0; mf < 2; mf++)
                #pragma unroll
                for (int np = 0; np < 2; np++) {
                    mma16816(acc[mf][np * 2 + 0], al[mf], bfr[np][0], bfr[np][2]);
                    mma16816(acc[mf][np * 2 + 1], al[mf], bfr[np][1], bfr[np][3]);
                }
            #pragma unroll
            for (int np = 0; np < 2; np++) {
                int row = wn + np * 16 + lrow;
                LDSM_X4(bfr[np], sBl + (uint32_t)row * 128 + ((uint32_t)(kc ^ (row & 7)) << 4));
            }
            #pragma unroll
            for (int mf = 0; mf < 2; mf++)
                #pragma unroll
                for (int np = 0; np < 2; np++) {
                    mma16816(acc[mf][np * 2 + 0], ah[mf], bfr[np][0], bfr[np][2]);
                    mma16816(acc[mf][np * 2 + 1], ah[mf], bfr[np][1], bfr[np][3]);
                }
        }
        __syncthreads();
    }

    #pragma unroll
    for (int mf = 0; mf < 2; mf++) {
        int t = t0 + wm + mf * 16 + (lane >> 2);
        #pragma unroll
        for (int nf = 0; nf < 4; nf++) {
            int n = h * HD + wn + ((nf >> 1) << 4) + ((nf & 1) << 3) + (lane & 3) * 2;
            split_store2(aoh, aol, ((size_t)b * CDIM + t) * SPAT + n,
                         acc[mf][nf][0], acc[mf][nf][1]);
            split_store2(aoh, aol, ((size_t)b * CDIM + t + 8) * SPAT + n,
                         acc[mf][nf][2], acc[mf][nf][3]);
        }
    }
}

// ---------------- output projection via MMA, 2-stage pipeline --------------
__global__ __launch_bounds__(256)
void proj_mma(const __nv_bfloat16* __restrict__ aoh, const __nv_bfloat16* __restrict__ aol,
              const __nv_bfloat16* __restrict__ woh, const __nv_bfloat16* __restrict__ wol,
              const float* __restrict__ bo, float* __restrict__ out) {
    extern __shared__ char smem[];
    const uint32_t sb = smem_u32(smem);
    const int tid = threadIdx.x, wid = tid >> 5, lane = tid & 31;
    const int row0 = blockIdx.y * 128, m0 = blockIdx.x * 128;

    const __nv_bfloat16* Ah = aoh + (size_t)row0 * CDIM;
    const __nv_bfloat16* Al = aol + (size_t)row0 * CDIM;
    const __nv_bfloat16* Bh = woh + (size_t)m0 * CDIM;
    const __nv_bfloat16* Bl = wol + (size_t)m0 * CDIM;

    const int wm = (wid & 3) * 32, wn = (wid >> 2) * 64;
    const int lrow = lane & 15, lkc = lane >> 4;

    float acc[2][8][4];
    #pragma unroll
    for (int i = 0; i < 2; i++)
        #pragma unroll
        for (int j = 0; j < 8; j++)
            #pragma unroll
            for (int q = 0; q < 4; q++) acc[i][j][q] = 0.f;

    auto load_stage = [&](int s, int it) {
        uint32_t base = sb + s * CONV_STAGE;
        #pragma unroll
        for (int p = 0; p < 4; p++) {
            int ci = tid + p * 256;
            int row = ci >> 3, c = ci & 7;
            uint32_t off = (uint32_t)row * 128 + ((uint32_t)(c ^ (row & 7)) << 4);
            cp_async16(base + off, Ah + (size_t)row * CDIM + it * 64 + c * 8, 16);
            cp_async16(base + 16384 + off, Al + (size_t)row * CDIM + it * 64 + c * 8, 16);
            cp_async16(base + 32768 + off, Bh + (size_t)row * CDIM + it * 64 + c * 8, 16);
            cp_async16(base + 49152 + off, Bl + (size_t)row * CDIM + it * 64 + c * 8, 16);
        }
        CP_COMMIT();
    };

    load_stage(0, 0);
    for (int it = 0; it < 16; it++) {
        int s = it & 1;
        if (it + 1 < 16) { load_stage(s ^ 1, it + 1); CP_WAIT(1); }
        else             { CP_WAIT(0); }
        __syncthreads();

        const uint32_t sAh = sb + s * CONV_STAGE;
        const uint32_t sAl = sAh + 16384, sBh = sAh + 32768, sBl = sAh + 49152;
        #pragma unroll
        for (int ks = 0; ks < 4; ks++) {
            const int kc = ks * 2 + lkc;
            uint32_t ah[2][4], al[2][4], bfr[4][4];
            #pragma unroll
            for (int mf = 0; mf < 2; mf++) {
                int row = wm + mf * 16 + lrow;
                LDSM_X4(ah[mf], sAh + (uint32_t)row * 128 + ((uint32_t)(kc ^ (row & 7)) << 4));
            }
            #pragma unroll
            for (int np = 0; np < 4; np++) {
                int row = wn + np * 16 + lrow;
                LDSM_X4(bfr[np], sBh + (uint32_t)row * 128 + ((uint32_t)(kc ^ (row & 7)) << 4));
            }
            #pragma unroll
            for (int mf = 0; mf < 2; mf++)
                #pragma unroll
                for (int np = 0; np < 4; np++) {
                    mma16816(acc[mf][np * 2 + 0], ah[mf], bfr[np][0], bfr[np][2]);
                    mma16816(acc[mf][np * 2 + 1], ah[mf], bfr[np][1], bfr[np][3]);
                }
            #pragma unroll
            for (int mf = 0; mf < 2; mf++) {
                int row = wm + mf * 16 + lrow;
                LDSM_X4(al[mf], sAl + (uint32_t)row * 128 + ((uint32_t)(kc ^ (row & 7)) << 4));
            }
            #pragma unroll
            for (int mf = 0; mf < 2; mf++)
                #pragma unroll
                for (int np = 0; np < 4; np++) {
                    mma16816(acc[mf][np * 2 + 0], al[mf], bfr[np][0], bfr[np][2]);
                    mma16816(acc[mf][np * 2 + 1], al[mf], bfr[np][1], bfr[np][3]);
                }
            #pragma unroll
            for (int np = 0; np < 4; np++) {
                int row = wn + np * 16 + lrow;
                LDSM_X4(bfr[np], sBl + (uint32_t)row * 128 + ((uint32_t)(kc ^ (row & 7)) << 4));
            }
            #pragma unroll
            for (int mf = 0; mf < 2; mf++)
                #pragma unroll
                for (int np = 0; np < 4; np++) {
                    mma16816(acc[mf][np * 2 + 0], ah[mf], bfr[np][0], bfr[np][2]);
                    mma16816(acc[mf][np * 2 + 1], ah[mf], bfr[np][1], bfr[np][3]);
                }
        }
        __syncthreads();
    }

    #pragma unroll
    for (int mf = 0; mf < 2; mf++) {
        int r = row0 + wm + mf * 16 + (lane >> 2);
        #pragma unroll
        for (int nf = 0; nf < 8; nf++) {
            int n = m0 + wn + ((nf >> 1) << 4) + ((nf & 1) << 3) + (lane & 3) * 2;
            float b0 = bo[n], b1 = bo[n + 1];
            float2 v0 = {acc[mf][nf][0] + b0, acc[mf][nf][1] + b1};
            float2 v1 = {acc[mf][nf][2] + b0, acc[mf][nf][3] + b1};
            *(float2*)(out + (size_t)r * CDIM + n) = v0;
            *(float2*)(out + (size_t)(r + 8) * CDIM + n) = v1;
        }
    }
}

// ---------------- launch ---------------------------------------------------
extern "C" void kernel_launch(void* const* d_in, const int* in_sizes, int n_in,
                              void* d_out, int out_size) {
    const float* q  = (const float*)d_in[0];
    const float* k  = (const float*)d_in[1];
    const float* v  = (const float*)d_in[2];
    const float* Wq = (const float*)d_in[3];
    const float* bq = (const float*)d_in[4];
    const float* Wk = (const float*)d_in[5];
    const float* bk = (const float*)d_in[6];
    const float* Wv = (const float*)d_in[7];
    const float* bv = (const float*)d_in[8];
    const float* Wo = (const float*)d_in[9];
    const float* bo = (const float*)d_in[10];
    const int*   mask = (const int*)d_in[11];
    float* out = (float*)d_out;

    __nv_bfloat16 *whi, *wlo, *ihi, *ilo, *chi, *clo, *vthi, *vtlo;
    __nv_bfloat16 *wohi, *wolo, *phi, *plo, *aoh, *aol;
    float *attn;
    cudaGetSymbolAddress((void**)&whi, g_whi);
    cudaGetSymbolAddress((void**)&wlo, g_wlo);
    cudaGetSymbolAddress((void**)&ihi, g_ihi);
    cudaGetSymbolAddress((void**)&ilo, g_ilo);
    cudaGetSymbolAddress((void**)&chi, g_chi);
    cudaGetSymbolAddress((void**)&clo, g_clo);
    cudaGetSymbolAddress((void**)&vthi, g_vthi);
    cudaGetSymbolAddress((void**)&vtlo, g_vtlo);
    cudaGetSymbolAddress((void**)&wohi, g_wohi);
    cudaGetSymbolAddress((void**)&wolo, g_wolo);
    cudaGetSymbolAddress((void**)&phi, g_phi);
    cudaGetSymbolAddress((void**)&plo, g_plo);
    cudaGetSymbolAddress((void**)&aoh, g_aohi);
    cudaGetSymbolAddress((void**)&aol, g_aolo);
    cudaGetSymbolAddress((void**)&attn, g_attn);

    cudaFuncSetAttribute(conv_mma, cudaFuncAttributeMaxDynamicSharedMemorySize, 2 * CONV_STAGE);
    cudaFuncSetAttribute(qk_mma,   cudaFuncAttributeMaxDynamicSharedMemorySize, 65536);
    cudaFuncSetAttribute(pv_mma,   cudaFuncAttributeMaxDynamicSharedMemorySize, 2 * PV_STAGE);
    cudaFuncSetAttribute(proj_mma, cudaFuncAttributeMaxDynamicSharedMemorySize, 2 * CONV_STAGE);

    split_w<<<dim3(CDIM, 3), 256>>>(Wq, Wk, Wv, whi, wlo);
    split_wo<<<4096, 256>>>(Wo, wohi, wolo);
    transpose_split_in<<<dim3(32, 32, 24), dim3(32, 8)>>>(q, k, v, ihi, ilo);

    conv_mma<<<dim3(8, 8, 24), 256, 2 * CONV_STAGE>>>(whi, wlo, ihi, ilo, bq, bk, bv, chi, clo);

    tr_bf16<<<dim3(32, 32, 8), dim3(32, 8)>>>(chi + (size_t)16 * CDIM * SPAT, vthi);
    tr_bf16<<<dim3(32, 32, 8), dim3(32, 8)>>>(clo + (size_t)16 * CDIM * SPAT, vtlo);

    qk_mma<<<dim3(8, 8, BATCH * NH), 256, 65536>>>(chi, clo, mask, attn);
    softmax_split<<<BATCH * NH * CDIM, 256>>>(attn, phi, plo);
    pv_mma<<<dim3(8, 1, BATCH * NH), 256, 2 * PV_STAGE>>>(phi, plo, vthi, vtlo, aoh, aol);

    proj_mma<<<dim3(8, 64), 256, 2 * CONV_STAGE>>>(aoh, aol, wohi, wolo, bo, out);
}